// round 10
// baseline (speedup 1.0000x reference)
#include <cuda_runtime.h>
#include <math.h>

// Fast MDCT: B=8, T=2^20, F=2048, hop=1024, N=1024, n_frames=1025.
// fold 2048 real -> DCT-IV -> 512-pt complex FFT (3 radix-8 Stockham stages).
// Persistent CTAs; smem trig tables; XOR-swizzled bufA (ping-pong);
// stage-2->3 exchange is WARP-LOCAL (sigma remap) via dedicated conflict-free
// layout: 1 named barrier + 1 syncwarp per frame.

#define NBINS 1024
#define SWZ(i) ((i) ^ (((i) >> 4) & 7) ^ ((((i) >> 6) & 1) << 3))
#define NGROUPS 5
#define NTHREADS (64 * NGROUPS)          // 320
#define GROUP_F2 1536                     // bufA0(512) + bufA1(512) + xbuf(512)
#define TBL_F2 (1024 + 64 + 64 + 56)      // qtbl(f4=1024 f2), postrowP, tw1row, tw2
#define SMEM_F2 (TBL_F2 + NGROUPS * GROUP_F2)
#define SMEM_BYTES (SMEM_F2 * (int)sizeof(float2))
#define NUM_CTAS 456                      // 152 SMs * 3 CTAs

#define PI_F 3.14159265358979323846f
#define SCALE 0.04419417382415922f        // sqrt(2/1024)
// u = exp(-i*pi/16)
#define UC 0.98078528040323044913f
#define US (-0.19509032201612826785f)

__device__ __forceinline__ float2 cmulf(float2 a, float2 b) {
    return make_float2(a.x * b.x - a.y * b.y, a.x * b.y + a.y * b.x);
}
__device__ __forceinline__ float2 caddf(float2 a, float2 b) { return make_float2(a.x + b.x, a.y + b.y); }
__device__ __forceinline__ float2 csubf(float2 a, float2 b) { return make_float2(a.x - b.x, a.y - b.y); }

__device__ __forceinline__ void dft8(const float2 a[8], float2 A[8]) {
    float2 e0 = caddf(a[0], a[4]), o0 = csubf(a[0], a[4]);
    float2 e1 = caddf(a[1], a[5]), o1 = csubf(a[1], a[5]);
    float2 e2 = caddf(a[2], a[6]), o2 = csubf(a[2], a[6]);
    float2 e3 = caddf(a[3], a[7]), o3 = csubf(a[3], a[7]);

    const float C = 0.70710678118654752f;
    float2 p1 = make_float2(C * (o1.x + o1.y), C * (o1.y - o1.x));
    float2 p2 = make_float2(o2.y, -o2.x);
    float2 p3 = make_float2(C * (o3.y - o3.x), -C * (o3.x + o3.y));

    float2 t0 = caddf(e0, e2), t1 = csubf(e0, e2);
    float2 t2 = caddf(e1, e3), t3 = csubf(e1, e3);
    A[0] = caddf(t0, t2);
    A[4] = csubf(t0, t2);
    A[2] = make_float2(t1.x + t3.y, t1.y - t3.x);
    A[6] = make_float2(t1.x - t3.y, t1.y + t3.x);

    float2 s0 = caddf(o0, p2), s1 = csubf(o0, p2);
    float2 s2 = caddf(p1, p3), s3 = csubf(p1, p3);
    A[1] = caddf(s0, s2);
    A[5] = csubf(s0, s2);
    A[3] = make_float2(s1.x + s3.y, s1.y - s3.x);
    A[7] = make_float2(s1.x - s3.y, s1.y + s3.x);
}

// Fused fold+pre-twiddle, q = (wc*ac, ws*ac, ws*as, wc*as)
__device__ __forceinline__ float2 foldA(float x0, float x1, float x2, float x3, float4 q) {
    return make_float2(-x0 * q.x - x1 * q.y - x2 * q.z + x3 * q.w,
                       -x0 * q.w - x1 * q.z + x2 * q.y - x3 * q.x);
}
__device__ __forceinline__ float2 foldB(float x0, float x1, float x2, float x3, float4 q) {
    return make_float2( x0 * q.y - x1 * q.x + x2 * q.w + x3 * q.z,
                        x0 * q.z - x1 * q.w - x2 * q.x - x3 * q.y);
}

__device__ __forceinline__ void fold_interior(
    const float* __restrict__ xf, int ROW,
    const float4* __restrict__ qtbl, float2 v[8])
{
#pragma unroll
    for (int s = 0; s < 4; s++) {
        const int na = ROW + 64 * s;
        const int nb = ROW + 64 * (7 - s);

        float2 fA1 = *(const float2*)(xf + 1536 + 2 * na);
        float2 fA3 = *(const float2*)(xf + 512 + 2 * na);
        float2 fB0 = *(const float2*)(xf + 2 * nb - 512);
        float2 fB2 = *(const float2*)(xf + 512 + 2 * nb);

        float oA0 = __shfl_xor_sync(0xffffffffu, fB2.y, 16);
        float oA2 = __shfl_xor_sync(0xffffffffu, fB0.y, 16);
        float oB3 = __shfl_xor_sync(0xffffffffu, fA1.y, 16);
        float oB1 = __shfl_xor_sync(0xffffffffu, fA3.y, 16);

        v[s]     = foldA(oA0, fA1.x, oA2, fA3.x, qtbl[na]);
        v[7 - s] = foldB(fB0.x, oB1, fB2.x, oB3, qtbl[nb]);
    }
}

__device__ __forceinline__ void fold_edge(
    const float* __restrict__ xb, int start, int T, int ROW,
    const float4* __restrict__ qtbl, float2 v[8])
{
#pragma unroll
    for (int j = 0; j < 8; j++) {
        int n = ROW + 64 * j;
        int i0, i1, i2, i3;
        if (j < 4) { i0 = 1535 - 2 * n; i1 = 1536 + 2 * n; i2 = 511 - 2 * n;  i3 = 512 + 2 * n; }
        else       { i0 = 2 * n - 512;  i1 = 1535 - 2 * n; i2 = 512 + 2 * n;  i3 = 2559 - 2 * n; }

        int g0 = start + i0, g1 = start + i1, g2 = start + i2, g3 = start + i3;
        float x0 = ((unsigned)g0 < (unsigned)T) ? xb[g0] : 0.f;
        float x1 = ((unsigned)g1 < (unsigned)T) ? xb[g1] : 0.f;
        float x2 = ((unsigned)g2 < (unsigned)T) ? xb[g2] : 0.f;
        float x3 = ((unsigned)g3 < (unsigned)T) ? xb[g3] : 0.f;

        v[j] = (j < 4) ? foldA(x0, x1, x2, x3, qtbl[n])
                       : foldB(x0, x1, x2, x3, qtbl[n]);
    }
}

// Warp-local exchange slot: class tile sg (8 lanes), producer offset p, reg t.
// Verified bijective on [0,512) and conflict-free for writes (fixed t) and
// reads (fixed p) per 16-lane phase.
__device__ __forceinline__ int PX(int sg, int p, int t) {
    return (sg << 6) | (((p >> 1) & 3) << 4) | (((p ^ t) & 1) << 3)
         | ((t ^ (p & 6) ^ sg) & 7);
}

__global__ __launch_bounds__(NTHREADS, 3) void mdct_main(
    const float* __restrict__ x, float* __restrict__ out,
    int T, int n_frames, int total_frames)
{
    extern __shared__ float2 smem2[];
    float4* qtbl     = (float4*)smem2;           // 512 f4
    float2* postrowP = smem2 + 1024;             // 64, lane-indexed (sigma map)
    float2* tw1row   = postrowP + 64;            // 64: exp(-i*pi*r/256)
    float2* tw2      = tw1row + 64;              // 56: [t-1][p] = exp(-i*pi*t*p/32)
    float2* gbuf     = tw2 + 56;

    const int tid = threadIdx.x;
    const int g = tid >> 6;
    const int l = tid & 63;

    // ---- per-CTA tables ----
    for (int n = tid; n < 512; n += NTHREADS) {
        float ws, wc, as_, ac;
        float targ = (n < 256) ? (511.5f - 2.0f * n) : (2.0f * n - 511.5f);
        __sincosf(targ * (PI_F / 2048.0f), &ws, &wc);
        __sincosf(-(float)n * (PI_F / 1024.0f), &as_, &ac);
        qtbl[n] = make_float4(wc * ac, ws * ac, ws * as_, wc * as_);
    }
    if (tid < 64) {
        // postrowP indexed by LANE: lane j handles butterfly r3 = q(j>>3) + 8*(j&7)
        int s_ = tid >> 3, t3 = tid & 7;
        int q_ = (s_ & 1) ? (7 - (s_ >> 1)) : (s_ >> 1);
        int r3 = q_ + 8 * t3;
        float s, c;
        __sincosf(-(4.0f * r3 + 1.0f) * (PI_F / 4096.0f), &s, &c);
        postrowP[tid] = make_float2(SCALE * c, SCALE * s);
        __sincosf(-(float)tid * (PI_F / 256.0f), &s, &c);
        tw1row[tid] = make_float2(c, s);
    } else if (tid >= 64 && tid < 120) {
        int i = tid - 64;
        int t = (i >> 3) + 1, p = i & 7;
        float s, c;
        __sincosf(-(float)(t * p) * (PI_F / 32.0f), &s, &c);
        tw2[i] = make_float2(c, s);
    }
    __syncthreads();

    float2* base = gbuf + g * GROUP_F2;
    float2* xbuf = base + 1024;                  // per-group exchange buffer

    // Stage-1 ROW map: butterflies r, 63-r at lanes l, l^16 (same warp)
    const int rbase = (l & 15) | (l & 32);
    const int ROW = (l & 16) ? (63 - rbase) : rbase;

    // Stage-2/3 sigma map: tile s = l>>3, class q = sigma^-1(s), offset p2 = l&7
    const int s_t = l >> 3;
    const int p2 = l & 7;
    const int qc = (s_t & 1) ? (7 - (s_t >> 1)) : (s_t >> 1);
    const int i2 = qc + 8 * p2;                  // stage-2 butterfly index
    const int r3 = qc + 8 * p2;                  // stage-3 butterfly index (t3 = p2)

    #define GBAR() asm volatile("bar.sync %0, 64;" :: "r"(g + 1) : "memory")

    int par = 0;
    for (int fi = blockIdx.x * NGROUPS + g; fi < total_frames;
         fi += (int)gridDim.x * NGROUPS) {

        const int b = fi / n_frames;
        const int f = fi - b * n_frames;
        const float* xb = x + (size_t)b * (size_t)T;
        const int start = f * 1024 - 1024;
        const bool interior = (start >= 0) && (start + 2048 <= T);
        float2* bA = base + par * 512;

        // ---- fold + pre-twiddle + stage-1 radix-8 (butterfly ROW) ----
        {
            float2 v[8];
            if (interior) fold_interior(xb + start, ROW, qtbl, v);
            else          fold_edge(xb, start, T, ROW, qtbl, v);

            float2 A[8];
            dft8(v, A);
            float2 w1 = tw1row[ROW];
            float2 wt = w1;
            A[1] = cmulf(A[1], wt);
#pragma unroll
            for (int t = 2; t < 8; t++) {
                wt = cmulf(wt, w1);
                A[t] = cmulf(A[t], wt);
            }
#pragma unroll
            for (int t = 0; t < 8; t++) bA[SWZ(8 * ROW + t)] = A[t];
        }
        GBAR();

        // ---- stage 2 radix-8 (butterfly i2) + warp-local exchange write ----
        {
            float2 a[8];
#pragma unroll
            for (int t = 0; t < 8; t++) a[t] = bA[SWZ(i2 + 64 * t)];
            float2 A[8];
            dft8(a, A);
#pragma unroll
            for (int t = 1; t < 8; t++) A[t] = cmulf(A[t], tw2[(t - 1) * 8 + p2]);
#pragma unroll
            for (int t = 0; t < 8; t++) xbuf[PX(s_t, p2, t)] = A[t];
        }
        __syncwarp();

        // ---- stage 3 radix-8 (butterfly r3) + post-twiddle + paired store ----
        {
            float2 a[8];
#pragma unroll
            for (int u = 0; u < 8; u++) a[u] = xbuf[PX(s_t, u, p2)];
            float2 A[8];
            dft8(a, A);

            const float2 u16 = make_float2(UC, US);
            float2 pt = postrowP[l];
            float2 P[8];
            P[0] = cmulf(A[0], pt);
#pragma unroll
            for (int t = 1; t < 8; t++) {
                pt = cmulf(pt, u16);
                P[t] = cmulf(A[t], pt);
            }

            float* ob = out + (size_t)fi * (size_t)NBINS;
#pragma unroll
            for (int t = 0; t < 8; t++) {
                // partner lane l^15 holds butterfly 63-r3; its P[7-t] is bin 511-(r3+64t)
                float odd = __shfl_xor_sync(0xffffffffu, -P[7 - t].y, 15);
                int r = r3 + 64 * t;
                *(float2*)(ob + 2 * r) = make_float2(P[t].x, odd);
            }
        }
        par ^= 1;
    }
    #undef GBAR
}

extern "C" void kernel_launch(void* const* d_in, const int* in_sizes, int n_in,
                              void* d_out, int out_size) {
    const float* x = (const float*)d_in[0];
    float* out = (float*)d_out;

    const int B = 8;
    const int T = in_sizes[0] / B;        // 1<<20
    const int n_frames = T / 1024 + 1;    // 1025
    const int total_frames = B * n_frames;

    static bool attr_set = false;
    if (!attr_set) {
        cudaFuncSetAttribute(mdct_main, cudaFuncAttributeMaxDynamicSharedMemorySize,
                             SMEM_BYTES);
        attr_set = true;
    }

    mdct_main<<<NUM_CTAS, NTHREADS, SMEM_BYTES>>>(x, out, T, n_frames, total_frames);
}

// round 11
// speedup vs baseline: 1.0755x; 1.0755x over previous
#include <cuda_runtime.h>
#include <math.h>

// Fast MDCT: B=8, T=2^20, F=2048, hop=1024, N=1024, n_frames=1025.
// fold 2048 real -> DCT-IV -> 512-pt complex FFT (3 radix-8 Stockham stages).
// Persistent CTAs; per-CTA smem trig tables; XOR-swizzled buffers;
// dense float2 fold loads with warp-shuffle redistribution.
// Round 10: contiguous frame chunks per group (L1 reuse of 50% frame overlap),
// 2 barriers per frame.

#define NBINS 1024
#define SWZ(i) ((i) ^ (((i) >> 4) & 7) ^ ((((i) >> 6) & 1) << 3))
#define BUF_F2 512
#define GROUP_F2 (2 * BUF_F2)
#define NGROUPS 4
#define NTHREADS (64 * NGROUPS)
#define TBL_F2 (512 + 512 + 512 + 448 + 56)   // wpair, apre, post, tw1, tw2
#define SMEM_F2 (TBL_F2 + NGROUPS * GROUP_F2)
#define SMEM_BYTES (SMEM_F2 * (int)sizeof(float2))
#define NUM_CTAS 608

#define PI_F 3.14159265358979323846f
#define SCALE 0.04419417382415922f    // sqrt(2/1024)

__device__ __forceinline__ float2 cmulf(float2 a, float2 b) {
    return make_float2(a.x * b.x - a.y * b.y, a.x * b.y + a.y * b.x);
}
__device__ __forceinline__ float2 caddf(float2 a, float2 b) { return make_float2(a.x + b.x, a.y + b.y); }
__device__ __forceinline__ float2 csubf(float2 a, float2 b) { return make_float2(a.x - b.x, a.y - b.y); }

__device__ __forceinline__ void dft8(const float2 a[8], float2 A[8]) {
    float2 e0 = caddf(a[0], a[4]), o0 = csubf(a[0], a[4]);
    float2 e1 = caddf(a[1], a[5]), o1 = csubf(a[1], a[5]);
    float2 e2 = caddf(a[2], a[6]), o2 = csubf(a[2], a[6]);
    float2 e3 = caddf(a[3], a[7]), o3 = csubf(a[3], a[7]);

    const float C = 0.70710678118654752f;
    float2 p1 = make_float2(C * (o1.x + o1.y), C * (o1.y - o1.x));
    float2 p2 = make_float2(o2.y, -o2.x);
    float2 p3 = make_float2(C * (o3.y - o3.x), -C * (o3.x + o3.y));

    float2 t0 = caddf(e0, e2), t1 = csubf(e0, e2);
    float2 t2 = caddf(e1, e3), t3 = csubf(e1, e3);
    A[0] = caddf(t0, t2);
    A[4] = csubf(t0, t2);
    A[2] = make_float2(t1.x + t3.y, t1.y - t3.x);
    A[6] = make_float2(t1.x - t3.y, t1.y + t3.x);

    float2 s0 = caddf(o0, p2), s1 = csubf(o0, p2);
    float2 s2 = caddf(p1, p3), s3 = csubf(p1, p3);
    A[1] = caddf(s0, s2);
    A[5] = csubf(s0, s2);
    A[3] = make_float2(s1.x + s3.y, s1.y - s3.x);
    A[7] = make_float2(s1.x - s3.y, s1.y + s3.x);
}

__device__ __forceinline__ float2 foldA(float x0, float x1, float x2, float x3,
                                        float2 w, float2 a) {
    float E = -(w.x * x0 + w.y * x1);
    float O =   w.y * x2 - w.x * x3;
    return make_float2(E * a.x - O * a.y, E * a.y + O * a.x);
}
__device__ __forceinline__ float2 foldB(float x0, float x1, float x2, float x3,
                                        float2 w, float2 a) {
    float E =   w.y * x0 - w.x * x1;
    float O = -(w.x * x2 + w.y * x3);
    return make_float2(E * a.x - O * a.y, E * a.y + O * a.x);
}

// Interior fold: dense float2 loads; odd elements swapped with lane^16.
__device__ __forceinline__ void fold_interior(
    const float* __restrict__ xf, int ROW,
    const float2* __restrict__ wpair, const float2* __restrict__ apre,
    float2 v[8])
{
#pragma unroll
    for (int s = 0; s < 4; s++) {
        const int na = ROW + 64 * s;          // branch A (n < 256)
        const int nb = ROW + 64 * (7 - s);    // branch B (n >= 256)

        float2 fA1 = *(const float2*)(xf + 1536 + 2 * na);
        float2 fA3 = *(const float2*)(xf + 512 + 2 * na);
        float2 fB0 = *(const float2*)(xf + 2 * nb - 512);
        float2 fB2 = *(const float2*)(xf + 512 + 2 * nb);

        float oA0 = __shfl_xor_sync(0xffffffffu, fB2.y, 16);  // y[1535-2na]
        float oA2 = __shfl_xor_sync(0xffffffffu, fB0.y, 16);  // y[511-2na]
        float oB3 = __shfl_xor_sync(0xffffffffu, fA1.y, 16);  // y[2559-2nb]
        float oB1 = __shfl_xor_sync(0xffffffffu, fA3.y, 16);  // y[1535-2nb]

        v[s]     = foldA(oA0, fA1.x, oA2, fA3.x, wpair[na], apre[na]);
        v[7 - s] = foldB(fB0.x, oB1, fB2.x, oB3, wpair[nb], apre[nb]);
    }
}

// Edge fold: scalar guarded loads (frames touching the zero padding).
__device__ __forceinline__ void fold_edge(
    const float* __restrict__ xb, int start, int T, int ROW,
    const float2* __restrict__ wpair, const float2* __restrict__ apre,
    float2 v[8])
{
#pragma unroll
    for (int j = 0; j < 8; j++) {
        int n = ROW + 64 * j;
        int i0, i1, i2, i3;
        if (j < 4) { i0 = 1535 - 2 * n; i1 = 1536 + 2 * n; i2 = 511 - 2 * n;  i3 = 512 + 2 * n; }
        else       { i0 = 2 * n - 512;  i1 = 1535 - 2 * n; i2 = 512 + 2 * n;  i3 = 2559 - 2 * n; }

        int g0 = start + i0, g1 = start + i1, g2 = start + i2, g3 = start + i3;
        float x0 = ((unsigned)g0 < (unsigned)T) ? xb[g0] : 0.f;
        float x1 = ((unsigned)g1 < (unsigned)T) ? xb[g1] : 0.f;
        float x2 = ((unsigned)g2 < (unsigned)T) ? xb[g2] : 0.f;
        float x3 = ((unsigned)g3 < (unsigned)T) ? xb[g3] : 0.f;

        v[j] = (j < 4) ? foldA(x0, x1, x2, x3, wpair[n], apre[n])
                       : foldB(x0, x1, x2, x3, wpair[n], apre[n]);
    }
}

__global__ __launch_bounds__(NTHREADS, 4) void mdct_main(
    const float* __restrict__ x, float* __restrict__ out,
    int T, int n_frames, int total_frames)
{
    extern __shared__ float2 smem2[];
    float2* wpair = smem2;              // 512
    float2* apre  = wpair + 512;        // 512
    float2* postt = apre + 512;         // 512 (scale folded in)
    float2* tw1   = postt + 512;        // 448: [t-1][r] = exp(-i*pi*t*r/256)
    float2* tw2   = tw1 + 448;          // 56:  [t-1][p] = exp(-i*pi*t*p/32)
    float2* gbuf  = tw2 + 56;

    const int tid = threadIdx.x;
    const int g = tid >> 6;
    const int l = tid & 63;

    // ---- per-CTA tables (fast MUFU trig; args <= 5.5 rad) ----
    for (int n = tid; n < 512; n += NTHREADS) {
        float s, c;
        float targ = (n < 256) ? (511.5f - 2.0f * n) : (2.0f * n - 511.5f);
        __sincosf(targ * (PI_F / 2048.0f), &s, &c);
        wpair[n] = make_float2(c, s);

        __sincosf(-(float)n * (PI_F / 1024.0f), &s, &c);
        apre[n] = make_float2(c, s);

        __sincosf(-(4.0f * n + 1.0f) * (PI_F / 4096.0f), &s, &c);
        postt[n] = make_float2(SCALE * c, SCALE * s);
    }
    for (int i = tid; i < 448; i += NTHREADS) {
        int t = (i >> 6) + 1, ll = i & 63;
        float s, c;
        __sincosf(-(float)(t * ll) * (PI_F / 256.0f), &s, &c);
        tw1[i] = make_float2(c, s);
    }
    if (tid < 56) {
        int t = (tid >> 3) + 1, p = tid & 7;
        float s, c;
        __sincosf(-(float)(t * p) * (PI_F / 32.0f), &s, &c);
        tw2[tid] = make_float2(c, s);
    }
    __syncthreads();

    float2* bufA = gbuf + g * GROUP_F2;
    float2* bufB = bufA + BUF_F2;

    // ROW permutation: butterflies r and 63-r at lanes l and l^16 (same warp)
    const int rbase = (l & 15) | (l & 32);
    const int ROW = (l & 16) ? (63 - rbase) : rbase;

    // Balanced CONTIGUOUS chunk of frames for this group: consecutive frames
    // overlap by 50%, so half the fold loads hit L1 (same SM, same warps).
    const int ngroups = (int)gridDim.x * NGROUPS;
    const int gidx = blockIdx.x * NGROUPS + g;
    const int fi_start = (int)(((long long)gidx * total_frames) / ngroups);
    const int fi_end   = (int)(((long long)(gidx + 1) * total_frames) / ngroups);

    #define GBAR() asm volatile("bar.sync %0, 64;" :: "r"(g + 1) : "memory")

    for (int fi = fi_start; fi < fi_end; fi++) {

        const int b = fi / n_frames;
        const int f = fi - b * n_frames;
        const float* xb = x + (size_t)b * (size_t)T;
        const int start = f * 1024 - 1024;
        const bool interior = (start >= 0) && (start + 2048 <= T);

        // ---- fold + pre-twiddle + stage-1 radix-8 (butterfly ROW) ----
        {
            float2 v[8];
            if (interior) fold_interior(xb + start, ROW, wpair, apre, v);
            else          fold_edge(xb, start, T, ROW, wpair, apre, v);

            float2 A[8];
            dft8(v, A);
#pragma unroll
            for (int t = 1; t < 8; t++) A[t] = cmulf(A[t], tw1[(t - 1) * 64 + ROW]);
#pragma unroll
            for (int t = 0; t < 8; t++) bufA[SWZ(8 * ROW + t)] = A[t];
        }
        GBAR();   // bar #1: bufA writes -> stage-2 reads; also orders prior
                  // stage-3 reads of bufB before next stage-2 writes it

        // ---- stage 2 radix-8 (butterfly l) ----
        {
            float2 a[8];
#pragma unroll
            for (int t = 0; t < 8; t++) a[t] = bufA[SWZ(l + 64 * t)];
            float2 A[8];
            dft8(a, A);
            int q = l & 7;
            int p = l >> 3;
#pragma unroll
            for (int t = 1; t < 8; t++) A[t] = cmulf(A[t], tw2[(t - 1) * 8 + p]);
            int j = q + 64 * p;
#pragma unroll
            for (int t = 0; t < 8; t++) bufB[SWZ(j + 8 * t)] = A[t];
        }
        GBAR();   // bar #2: bufB writes -> stage-3 reads; also orders stage-2
                  // reads of bufA before next frame's stage-1 writes it

        // ---- stage 3 radix-8 + post-twiddle + shfl-paired store ----
        {
            float2 a[8];
#pragma unroll
            for (int t = 0; t < 8; t++) a[t] = bufB[SWZ(ROW + 64 * t)];
            float2 A[8];
            dft8(a, A);
            float2 P[8];
#pragma unroll
            for (int t = 0; t < 8; t++) P[t] = cmulf(A[t], postt[ROW + 64 * t]);

            float* ob = out + (size_t)fi * (size_t)NBINS;
#pragma unroll
            for (int t = 0; t < 8; t++) {
                float odd = __shfl_xor_sync(0xffffffffu, -P[7 - t].y, 16);
                int r = ROW + 64 * t;
                *(float2*)(ob + 2 * r) = make_float2(P[t].x, odd);
            }
        }
        // no loop-end barrier: hazards covered by bars #1/#2 of next iteration
    }
    #undef GBAR
}

extern "C" void kernel_launch(void* const* d_in, const int* in_sizes, int n_in,
                              void* d_out, int out_size) {
    const float* x = (const float*)d_in[0];
    float* out = (float*)d_out;

    const int B = 8;
    const int T = in_sizes[0] / B;        // 1<<20
    const int n_frames = T / 1024 + 1;    // 1025
    const int total_frames = B * n_frames;

    static bool attr_set = false;
    if (!attr_set) {
        cudaFuncSetAttribute(mdct_main, cudaFuncAttributeMaxDynamicSharedMemorySize,
                             SMEM_BYTES);
        attr_set = true;
    }

    mdct_main<<<NUM_CTAS, NTHREADS, SMEM_BYTES>>>(x, out, T, n_frames, total_frames);
}